// round 1
// baseline (speedup 1.0000x reference)
#include <cuda_runtime.h>
#include <math.h>

#define NTOK 8192
#define DIM  1024
#define FFN  4096
#define NE   10

// ---------------- scratch (device globals: no allocation allowed) ----------
__device__ float g_A [(size_t)NTOK * FFN];   // gelu(x@W1+b1) activations
__device__ float g_H [(size_t)NTOK * DIM];   // h = A@W2 + b2 + x
__device__ float g_Xg[(size_t)NTOK * DIM];   // x gathered into expert order
__device__ int   g_perm[NTOK];
__device__ int   g_cnt[NE];
__device__ int   g_off[NE];
__device__ int   g_cur[NE];

// ---------------- routing ---------------------------------------------------
__global__ void k_zero() {
    int i = threadIdx.x;
    if (i < NE) { g_cnt[i] = 0; g_cur[i] = 0; }
}

__global__ void k_count(const int* __restrict__ ids) {
    int i = blockIdx.x * blockDim.x + threadIdx.x;
    if (i < NTOK) atomicAdd(&g_cnt[ids[i]], 1);
}

__global__ void k_scan() {
    if (threadIdx.x == 0) {
        int s = 0;
        for (int e = 0; e < NE; e++) { g_off[e] = s; s += g_cnt[e]; }
    }
}

__global__ void k_scatter(const int* __restrict__ ids) {
    int i = blockIdx.x * blockDim.x + threadIdx.x;
    if (i < NTOK) {
        int e = ids[i];
        int p = g_off[e] + atomicAdd(&g_cur[e], 1);
        g_perm[p] = i;
    }
}

__global__ void k_gather(const float* __restrict__ x) {
    int p   = blockIdx.x;
    int src = g_perm[p];
    const float4* s = (const float4*)(x + (size_t)src * DIM);
    float4*       d = (float4*)(g_Xg + (size_t)p * DIM);
    d[threadIdx.x] = s[threadIdx.x];   // 256 threads * float4 = 1024 floats
}

// ---------------- fused GEMM ------------------------------------------------
// MODE 0: C = gelu(A@B + bias)               -> g_A      (A = x or g_Xg)
// MODE 1: C = A@B + bias + xres              -> g_H      (A = g_A)
// MODE 2: g = sigmoid(A@B + bias); out = g*h + (1-g)*x   (A = x or g_Xg)
//         shared: Fout[row] = v ; domain: Fout[perm[row]] += v
template <int MODE, bool DOMAIN>
__global__ void __launch_bounds__(256, 2) gemm_k(
    const float* __restrict__ xin,      // x (shared path); domain path uses g_Xg
    const float* __restrict__ Bbase,    // weight base (domain: + e*K*Nd)
    const float* __restrict__ biasBase, // bias base   (domain: + e*Nd)
    float*       __restrict__ Fout,     // final output (MODE 2 only)
    int K, int Nd)
{
    int e = 0, Mloc = NTOK, rowBase = 0;
    if (DOMAIN) {
        e       = blockIdx.z;
        Mloc    = g_cnt[e];
        rowBase = g_off[e];
        if ((int)blockIdx.y * 128 >= Mloc) return;   // empty tile -> bail fast
    }

    const float* A;
    if (MODE == 1) A = g_A + (size_t)rowBase * K;
    else           A = (DOMAIN ? g_Xg : xin) + (size_t)rowBase * K;
    const float* B    = Bbase    + (DOMAIN ? (size_t)e * K * Nd : 0);
    const float* bias = biasBase + (DOMAIN ? (size_t)e * Nd     : 0);
    const float* Xr   = DOMAIN ? g_Xg : xin;   // residual / gate mix source

    __shared__ float As[8][128];
    __shared__ float Bs[8][128];

    int tid = threadIdx.x;
    int tx = tid & 15, ty = tid >> 4;

    // A tile load map: 1 float4 per thread, transpose into As[k][m]
    int am = tid >> 1;            // 0..127 (row in tile)
    int ak = (tid & 1) * 4;       // 0 or 4 (k offset)
    // B tile load map: coalesced float4, Bs[k][n]
    int bk = tid >> 5;            // 0..7
    int bn = (tid & 31) * 4;      // 0..124

    int rowTile = blockIdx.y * 128;
    int colTile = blockIdx.x * 128;

    bool aValid = (rowTile + am) < Mloc;
    const float* Aptr = A + (size_t)(rowTile + am) * K + ak;
    const float* Bptr = B + (size_t)bk * Nd + colTile + bn;

    float acc[8][8];
#pragma unroll
    for (int i = 0; i < 8; i++)
#pragma unroll
        for (int j = 0; j < 8; j++) acc[i][j] = 0.f;

    for (int kk = 0; kk < K; kk += 8) {
        float4 av = aValid ? *(const float4*)Aptr : make_float4(0.f, 0.f, 0.f, 0.f);
        float4 bv = *(const float4*)Bptr;

        As[ak + 0][am] = av.x;
        As[ak + 1][am] = av.y;
        As[ak + 2][am] = av.z;
        As[ak + 3][am] = av.w;
        *(float4*)&Bs[bk][bn] = bv;
        __syncthreads();

#pragma unroll
        for (int k = 0; k < 8; k++) {
            float a[8], b[8];
            *(float4*)(a)     = *(const float4*)&As[k][ty * 8];
            *(float4*)(a + 4) = *(const float4*)&As[k][ty * 8 + 4];
            *(float4*)(b)     = *(const float4*)&Bs[k][tx * 8];
            *(float4*)(b + 4) = *(const float4*)&Bs[k][tx * 8 + 4];
#pragma unroll
            for (int i = 0; i < 8; i++)
#pragma unroll
                for (int j = 0; j < 8; j++)
                    acc[i][j] = fmaf(a[i], b[j], acc[i][j]);
        }
        Aptr += 8;
        Bptr += (size_t)8 * Nd;
        __syncthreads();
    }

    // ---------------- epilogue ----------------
    int col0 = colTile + tx * 8;
#pragma unroll
    for (int i = 0; i < 8; i++) {
        int lr = rowTile + ty * 8 + i;
        if (lr >= Mloc) continue;
        int grow = rowBase + lr;               // row in (permuted) activation space

        if (MODE == 0) {
            float* dst = g_A + (size_t)grow * Nd + col0;
#pragma unroll
            for (int j = 0; j < 8; j++) {
                float v = acc[i][j] + bias[col0 + j];
                dst[j] = 0.5f * v * (1.0f + erff(v * 0.70710678118654752f));
            }
        } else if (MODE == 1) {
            float*       dst = g_H + (size_t)grow * Nd + col0;
            const float* r   = Xr  + (size_t)grow * Nd + col0;
#pragma unroll
            for (int j = 0; j < 8; j++)
                dst[j] = acc[i][j] + bias[col0 + j] + r[j];
        } else {
            const float* hp = g_H + (size_t)grow * Nd + col0;
            const float* xp = Xr  + (size_t)grow * Nd + col0;
            int orow = DOMAIN ? g_perm[grow] : grow;
            float* dst = Fout + (size_t)orow * Nd + col0;
#pragma unroll
            for (int j = 0; j < 8; j++) {
                float gl = acc[i][j] + bias[col0 + j];
                float gv = 1.0f / (1.0f + expf(-gl));
                float v  = gv * hp[j] + (1.0f - gv) * xp[j];
                if (DOMAIN) dst[j] += v;       // unique writer per (token,col)
                else        dst[j]  = v;
            }
        }
    }
}

// ---------------- launch -----------------------------------------------------
extern "C" void kernel_launch(void* const* d_in, const int* in_sizes, int n_in,
                              void* d_out, int out_size)
{
    const float* x   = (const float*)d_in[0];
    const int*   ids = (const int*)  d_in[1];
    const float* sW1 = (const float*)d_in[2];
    const float* sb1 = (const float*)d_in[3];
    const float* sW2 = (const float*)d_in[4];
    const float* sb2 = (const float*)d_in[5];
    const float* sWg = (const float*)d_in[6];
    const float* sbg = (const float*)d_in[7];
    const float* dW1 = (const float*)d_in[8];
    const float* db1 = (const float*)d_in[9];
    const float* dW2 = (const float*)d_in[10];
    const float* db2 = (const float*)d_in[11];
    const float* dWg = (const float*)d_in[12];
    const float* dbg = (const float*)d_in[13];
    float* out = (float*)d_out;

    // routing
    k_zero   <<<1, 32>>>();
    k_count  <<<NTOK / 256, 256>>>(ids);
    k_scan   <<<1, 32>>>();
    k_scatter<<<NTOK / 256, 256>>>(ids);
    k_gather <<<NTOK, 256>>>(x);

    dim3 blk(256);

    // shared expert (all tokens)
    gemm_k<0, false><<<dim3(FFN / 128, NTOK / 128, 1), blk>>>(x, sW1, sb1, nullptr, DIM, FFN);
    gemm_k<1, false><<<dim3(DIM / 128, NTOK / 128, 1), blk>>>(x, sW2, sb2, nullptr, FFN, DIM);
    gemm_k<2, false><<<dim3(DIM / 128, NTOK / 128, 1), blk>>>(x, sWg, sbg, out,     DIM, DIM);

    // domain experts (grouped over expert buckets; empty tiles exit immediately)
    gemm_k<0, true><<<dim3(FFN / 128, NTOK / 128, NE), blk>>>(nullptr, dW1, db1, nullptr, DIM, FFN);
    gemm_k<1, true><<<dim3(DIM / 128, NTOK / 128, NE), blk>>>(nullptr, dW2, db2, nullptr, FFN, DIM);
    gemm_k<2, true><<<dim3(DIM / 128, NTOK / 128, NE), blk>>>(nullptr, dWg, dbg, out,     DIM, DIM);
}